// round 2
// baseline (speedup 1.0000x reference)
#include <cuda_runtime.h>

#define S_DIM 16
#define M_DIM 768
#define N_DIM 1024
#define TOTAL (S_DIM * M_DIM * N_DIM)
#define MAX_DISP 64.0f
#define INVALID_VAL 100.0f

__global__ __launch_bounds__(256) void lr_distance_kernel(
    const float* __restrict__ lr,
    const float* __restrict__ rl,
    float* __restrict__ out)
{
    int tid = blockIdx.x * blockDim.x + threadIdx.x;
    int idx4 = tid * 4;
    if (idx4 >= TOTAL) return;

    int s   = idx4 / (M_DIM * N_DIM);
    int rem = idx4 - s * (M_DIM * N_DIM);
    int y   = rem / N_DIM;
    int xb  = rem - y * N_DIM;   // base x for the 4-element group (row-aligned since N%4==0)

    // Row-constant vertical interpolation terms (same formula chain as reference)
    float yl_normed = 2.0f * (float)y / (float)(M_DIM - 1) - 1.0f;
    float iy = ((yl_normed + 1.0f) * (float)M_DIM - 1.0f) * 0.5f;
    float y0f = floorf(iy);
    float y1f = y0f + 1.0f;
    float wy1 = iy - y0f;
    float wy0 = 1.0f - wy1;
    bool  y0in = (y0f >= 0.0f) && (y0f <= (float)(M_DIM - 1));
    bool  y1in = (y1f >= 0.0f) && (y1f <= (float)(M_DIM - 1));
    int   y0i = min(max((int)y0f, 0), M_DIM - 1);
    int   y1i = min(max((int)y1f, 0), M_DIM - 1);

    const float* __restrict__ img  = rl + s * (M_DIM * N_DIM);
    const float* __restrict__ row0 = img + y0i * N_DIM;
    const float* __restrict__ row1 = img + y1i * N_DIM;

    float4 d4 = *reinterpret_cast<const float4*>(lr + idx4);
    float dvals[4] = {d4.x, d4.y, d4.z, d4.w};
    float res[4];

    #pragma unroll
    for (int j = 0; j < 4; j++) {
        float d  = dvals[j];
        float xl = (float)(xb + j);
        float xr = xl - d;

        bool invalid = (xr >= (float)N_DIM) || (xr < 0.0f);

        float xr_normed = 2.0f * xr / (float)(N_DIM - 1) - 1.0f;
        float ix = ((xr_normed + 1.0f) * (float)N_DIM - 1.0f) * 0.5f;

        float x0f = floorf(ix);
        float x1f = x0f + 1.0f;
        float wx1 = ix - x0f;
        float wx0 = 1.0f - wx1;
        bool  x0in = (x0f >= 0.0f) && (x0f <= (float)(N_DIM - 1));
        bool  x1in = (x1f >= 0.0f) && (x1f <= (float)(N_DIM - 1));
        int   x0i = min(max((int)x0f, 0), N_DIM - 1);
        int   x1i = min(max((int)x1f, 0), N_DIM - 1);

        float v00 = (y0in && x0in) ? __ldg(row0 + x0i) : 0.0f;
        float v01 = (y0in && x1in) ? __ldg(row0 + x1i) : 0.0f;
        float v10 = (y1in && x0in) ? __ldg(row1 + x0i) : 0.0f;
        float v11 = (y1in && x1in) ? __ldg(row1 + x1i) : 0.0f;

        float warped = (v00 * wx0 + v01 * wx1) * wy0
                     + (v10 * wx0 + v11 * wx1) * wy1;

        float dist = fabsf(d + warped);
        res[j] = invalid ? INVALID_VAL : dist;
    }

    float4 o4 = make_float4(res[0], res[1], res[2], res[3]);
    *reinterpret_cast<float4*>(out + idx4) = o4;
}

extern "C" void kernel_launch(void* const* d_in, const int* in_sizes, int n_in,
                              void* d_out, int out_size)
{
    const float* lr = (const float*)d_in[0];
    const float* rl = (const float*)d_in[1];
    float* out = (float*)d_out;

    int threads = 256;
    int groups  = TOTAL / 4;                 // 3,145,728 groups
    int blocks  = (groups + threads - 1) / threads;
    lr_distance_kernel<<<blocks, threads>>>(lr, rl, out);
}

// round 4
// speedup vs baseline: 1.0082x; 1.0082x over previous
#include <cuda_runtime.h>

#define S_DIM 16
#define M_DIM 768
#define N_DIM 1024
#define ROWS_PER_BLK 4
#define STAGE_ROWS 6          // ybase-1 .. ybase+4
#define LPAD 68               // covers x0 >= -65, 16B aligned
#define RPAD 4
#define RSTRIDE (LPAD + N_DIM + RPAD)   // 1096 floats, 4384 bytes
#define INVALID_VAL 100.0f

__global__ __launch_bounds__(256) void lr_distance_kernel(
    const float* __restrict__ lr,
    const float* __restrict__ rl,
    float* __restrict__ out)
{
    __shared__ float sm[STAGE_ROWS * RSTRIDE];   // 26304 bytes

    const int tid   = threadIdx.x;
    const int bid   = blockIdx.x;
    const int s     = bid / (M_DIM / ROWS_PER_BLK);
    const int grp   = bid % (M_DIM / ROWS_PER_BLK);
    const int ybase = grp * ROWS_PER_BLK;
    const int g0    = ybase - 1;                 // first staged global row

    const float* __restrict__ img = rl + s * (M_DIM * N_DIM);

    // Zero the pads: per staged row, left 68 + right 4 = 72 floats -> 432 total.
    // MUST be a loop: 432 > blockDim (this was the R2 bug).
    for (int v = tid; v < STAGE_ROWS * (LPAD + RPAD); v += 256) {
        int r = v / (LPAD + RPAD);
        int p = v % (LPAD + RPAD);
        int idx = (p < LPAD) ? p : (LPAD + N_DIM + (p - LPAD));
        sm[r * RSTRIDE + idx] = 0.0f;
    }

    // Stage 6 rows (zero-fill rows outside [0, M)): 6*256 float4 transfers
    #pragma unroll
    for (int v = tid; v < STAGE_ROWS * (N_DIM / 4); v += 256) {
        int r = v >> 8;          // v / 256
        int c = v & 255;         // v % 256
        int g = g0 + r;
        float4 val = make_float4(0.0f, 0.0f, 0.0f, 0.0f);
        if (g >= 0 && g < M_DIM)
            val = *reinterpret_cast<const float4*>(img + g * N_DIM + c * 4);
        *reinterpret_cast<float4*>(sm + r * RSTRIDE + LPAD + c * 4) = val;
    }
    __syncthreads();

    const int   xs  = tid * 4;
    const float xlb = (float)xs;
    const int   sbase = s * (M_DIM * N_DIM);

    #pragma unroll
    for (int r = 0; r < ROWS_PER_BLK; r++) {
        const int y = ybase + r;

        // Vertical terms (reference formula chain), once per row
        float yl  = 2.0f * (float)y / (float)(M_DIM - 1) - 1.0f;
        float iy  = ((yl + 1.0f) * (float)M_DIM - 1.0f) * 0.5f;
        float y0f = floorf(iy);
        float wy1 = iy - y0f;
        int   r0  = (int)y0f - g0;                 // staged row index, in [0,4]
        const float* __restrict__ rowb = sm + r0 * RSTRIDE;

        float4 dv = *reinterpret_cast<const float4*>(lr + sbase + y * N_DIM + xs);
        float dd[4] = {dv.x, dv.y, dv.z, dv.w};
        float res[4];

        #pragma unroll
        for (int j = 0; j < 4; j++) {
            float d  = dd[j];
            float xr = (xlb + (float)j) - d;

            // Reference expression chain (R1-verified rounding)
            float xr_normed = 2.0f * xr / (float)(N_DIM - 1) - 1.0f;
            float ix = ((xr_normed + 1.0f) * (float)N_DIM - 1.0f) * 0.5f;

            float x0f = floorf(ix);
            float wx1 = ix - x0f;
            int   idx = (int)x0f + LPAD;
            idx = max(0, min(idx, LPAD + N_DIM));   // pads absorb OOB taps

            float v00 = rowb[idx];
            float v01 = rowb[idx + 1];
            float v10 = rowb[idx + RSTRIDE];
            float v11 = rowb[idx + RSTRIDE + 1];

            float wx0 = 1.0f - wx1;
            float wy0 = 1.0f - wy1;
            float warped = (v00 * wx0 + v01 * wx1) * wy0
                         + (v10 * wx0 + v11 * wx1) * wy1;

            float dist = fabsf(d + warped);
            bool invalid = (xr < 0.0f) || (xr >= (float)N_DIM);
            res[j] = invalid ? INVALID_VAL : dist;
        }

        *reinterpret_cast<float4*>(out + sbase + y * N_DIM + xs) =
            make_float4(res[0], res[1], res[2], res[3]);
    }
}

extern "C" void kernel_launch(void* const* d_in, const int* in_sizes, int n_in,
                              void* d_out, int out_size)
{
    const float* lr = (const float*)d_in[0];
    const float* rl = (const float*)d_in[1];
    float* out = (float*)d_out;

    int blocks = S_DIM * (M_DIM / ROWS_PER_BLK);   // 16 * 192 = 3072
    lr_distance_kernel<<<blocks, 256>>>(lr, rl, out);
}